// round 16
// baseline (speedup 1.0000x reference)
#include <cuda_runtime.h>
#include <math.h>

// Problem constants (match reference)
#define N_INPUTSC 2048
#define UNITSC    2048
#define LC        8
#define FANINC    4096
#define TOTALC    18432

#define KC      32            // partial-sum depth (k-chunks of 128 rows)
#define RPC     128           // rows per chunk
#define JT      16            // column tiles of 128
#define CPB     128           // cols per tile
#define GEMV_BLOCKS (KC * JT) // 512
#define MAT_BLOCKS  8         // materialization blocks appended to the grid

// Persistent scratch (allocation-free rule: __device__ globals)
__device__ float g_partial[2][KC * UNITSC];  // ping-pong partials, 256KB each
__device__ float g_outputs[TOTALC];          // materialized state vector

// Sum the KC partials for column u of the previous layer (L2-resident).
__device__ __forceinline__ float sum_partials(const float* __restrict__ P, int u) {
    float s0 = 0.f, s1 = 0.f;
#pragma unroll
    for (int c = 0; c < KC; c += 2) {
        s0 += P[(size_t)c       * UNITSC + u];
        s1 += P[(size_t)(c + 1) * UNITSC + u];
    }
    return s0 + s1;
}

// Indivisible 4x LDG.128 batch: ptxas cannot re-roll or interleave inside a
// single asm block, so all 4 loads issue back-to-back (guaranteed MLP >= 4).
#define LOAD4X4(W0, W1, W2, W3, p0, p1, p2, p3)                              \
    asm volatile(                                                            \
        "ld.global.nc.v4.f32 {%0,%1,%2,%3},     [%16];\n\t"                  \
        "ld.global.nc.v4.f32 {%4,%5,%6,%7},     [%17];\n\t"                  \
        "ld.global.nc.v4.f32 {%8,%9,%10,%11},   [%18];\n\t"                  \
        "ld.global.nc.v4.f32 {%12,%13,%14,%15}, [%19];\n\t"                  \
        : "=f"(W0.x), "=f"(W0.y), "=f"(W0.z), "=f"(W0.w),                    \
          "=f"(W1.x), "=f"(W1.y), "=f"(W1.z), "=f"(W1.w),                    \
          "=f"(W2.x), "=f"(W2.y), "=f"(W2.z), "=f"(W2.w),                    \
          "=f"(W3.x), "=f"(W3.y), "=f"(W3.z), "=f"(W3.w)                     \
        : "l"(p0), "l"(p1), "l"(p2), "l"(p3))

// ---------------------------------------------------------------------------
// fused layer kernel, one launch per layer.
//  - blocks [0, 512): gemv. Block (kc, jt): rows [kc*128,+128), cols
//    [jt*128,+128). Prologue: 128 threads gather one element each. Main:
//    8 warps x 16 rows in 4 indivisible 4-load asm batches; dead rows
//    (gathered value 0) SEL-redirect to the warp base row (L1-resident) so
//    their DRAM bytes are skipped without any branch in the load stream.
//  - blocks [512, 520): materialize slice `layer` into g_outputs.
// ---------------------------------------------------------------------------
__global__ __launch_bounds__(256) void layer_kernel(
    int layer,
    const float* __restrict__ x,
    const int*   __restrict__ node_inds,
    const float* __restrict__ Ws,
    const float* __restrict__ bs)
{
    const int tid  = threadIdx.x;
    const int base = layer << 11;
    const float* Pprev = g_partial[(layer + 1) & 1];
    const float* bprev = bs + (layer - 1) * UNITSC;

    if (blockIdx.x >= GEMV_BLOCKS) {
        // ---- materialize slice `layer` ----
        int u = (blockIdx.x - GEMV_BLOCKS) * 256 + tid;
        float o;
        if (layer == 0) o = x[u];
        else            o = tanhf(sum_partials(Pprev, u) + bprev[u]);
        g_outputs[base + u] = o;
        return;
    }

    const int kc = blockIdx.x >> 4;
    const int jt = blockIdx.x & 15;

    __shared__ float  sg[RPC];
    __shared__ float4 red[8][32];

    // Prologue: one gather element per thread (first 128 threads).
    if (tid < RPC) {
        int idx = node_inds[layer * FANINC + kc * RPC + tid];
        float v = 0.f;
        if (idx < base) {
            v = g_outputs[idx];                  // older slice, materialized
        } else if (idx < base + UNITSC) {
            int u = idx - base;                  // current slice: recompute
            if (layer == 0) v = x[u];
            else            v = tanhf(sum_partials(Pprev, u) + bprev[u]);
        }
        sg[tid] = v;
    }
    __syncthreads();

    const int tx = tid & 31;
    const int tg = tid >> 5;                     // warp id: rows tg*16..+15
    const float* Wb = Ws + ((size_t)layer * FANINC + kc * RPC + tg * 16) * UNITSC
                    + jt * CPB + tx * 4;

    // Preload gathered values (breaks LDS out of the load-address chain).
    float gv[16];
#pragma unroll
    for (int i = 0; i < 16; ++i) gv[i] = sg[tg * 16 + i];

    float ax = 0.f, ay = 0.f, az = 0.f, aw = 0.f;
#pragma unroll
    for (int b = 0; b < 4; ++b) {
        // SEL addresses: dead rows -> warp base row (one L1-resident line).
        const float* p0 = (gv[b*4+0] != 0.f) ? Wb + (size_t)(b*4+0) * UNITSC : Wb;
        const float* p1 = (gv[b*4+1] != 0.f) ? Wb + (size_t)(b*4+1) * UNITSC : Wb;
        const float* p2 = (gv[b*4+2] != 0.f) ? Wb + (size_t)(b*4+2) * UNITSC : Wb;
        const float* p3 = (gv[b*4+3] != 0.f) ? Wb + (size_t)(b*4+3) * UNITSC : Wb;
        float4 w0, w1, w2, w3;
        LOAD4X4(w0, w1, w2, w3, p0, p1, p2, p3);
        ax = fmaf(gv[b*4+0], w0.x, ax); ay = fmaf(gv[b*4+0], w0.y, ay);
        az = fmaf(gv[b*4+0], w0.z, az); aw = fmaf(gv[b*4+0], w0.w, aw);
        ax = fmaf(gv[b*4+1], w1.x, ax); ay = fmaf(gv[b*4+1], w1.y, ay);
        az = fmaf(gv[b*4+1], w1.z, az); aw = fmaf(gv[b*4+1], w1.w, aw);
        ax = fmaf(gv[b*4+2], w2.x, ax); ay = fmaf(gv[b*4+2], w2.y, ay);
        az = fmaf(gv[b*4+2], w2.z, az); aw = fmaf(gv[b*4+2], w2.w, aw);
        ax = fmaf(gv[b*4+3], w3.x, ax); ay = fmaf(gv[b*4+3], w3.y, ay);
        az = fmaf(gv[b*4+3], w3.z, az); aw = fmaf(gv[b*4+3], w3.w, aw);
    }

    red[tg][tx] = make_float4(ax, ay, az, aw);
    __syncthreads();
    if (tg == 0) {
        float4 s = red[0][tx];
#pragma unroll
        for (int r = 1; r < 8; ++r) {
            float4 p = red[r][tx];
            s.x += p.x; s.y += p.y; s.z += p.z; s.w += p.w;
        }
        *reinterpret_cast<float4*>(g_partial[layer & 1]
                                   + kc * UNITSC + jt * CPB + tx * 4) = s;
    }
}

// ---------------------------------------------------------------------------
// final: out = tanh(colsum(layer-7 partials) + b7)
// ---------------------------------------------------------------------------
__global__ __launch_bounds__(256) void final_kernel(
    const float* __restrict__ bs, float* __restrict__ out)
{
    int u = blockIdx.x * 256 + threadIdx.x;
    const float* P = g_partial[(LC - 1) & 1];
    out[u] = tanhf(sum_partials(P, u) + bs[(LC - 1) * UNITSC + u]);
}

extern "C" void kernel_launch(void* const* d_in, const int* in_sizes, int n_in,
                              void* d_out, int out_size) {
    const float* x  = (const float*)d_in[0];   // [2048] f32
    const int*   ni = (const int*)d_in[1];     // [8, 4096] i32
    const float* Ws = (const float*)d_in[2];   // [8, 4096, 2048] f32
    const float* bs = (const float*)d_in[3];   // [8, 2048] f32
    float* out = (float*)d_out;                // [2048] f32

    for (int i = 0; i < LC; ++i) {
        layer_kernel<<<GEMV_BLOCKS + MAT_BLOCKS, 256>>>(i, x, ni, Ws, bs);
    }
    final_kernel<<<UNITSC / 256, 256>>>(bs, out);
}